// round 1
// baseline (speedup 1.0000x reference)
#include <cuda_runtime.h>
#include <cuda_bf16.h>
#include <cstdint>

// Problem shapes (fixed by the dataset)
#define B_  4
#define T_  8192
#define D_  512
#define H_  512
#define M_  (B_ * T_)        // 32768 rows

#define NCHUNK 32
#define TC     (T_ / NCHUNK) // 256

// Scratch (device globals: allocation-free rule)
__device__ float g_c[(size_t)M_ * H_];               // 64 MB: coeff  = sigmoid(-k)
__device__ float g_v[(size_t)M_ * H_];               // 64 MB: value  = sigmoid(k) * g(a)
__device__ float g_sumA[B_ * NCHUNK * H_];
__device__ float g_sumB[B_ * NCHUNK * H_];
__device__ float g_carry[B_ * NCHUNK * H_];

// ---------------------------------------------------------------------------
// Kernel 1: fused dual GEMM + gate epilogue.
//   k[m,n] = sum_d x[m,d] * Wz[n,d] + bz[n]
//   a[m,n] = sum_d x[m,d] * Wh[n,d] + bh[n]
//   g_c[m,n] = sigmoid(-k);  g_v[m,n] = sigmoid(k) * g(a)
// Tile: BM=128, BN=64, BK=16; 256 threads; per-thread 8x4 x 2 accumulators.
// ---------------------------------------------------------------------------
#define BM 128
#define BN 64
#define BK 16

__global__ __launch_bounds__(256, 2)
void gemm_gate_kernel(const float* __restrict__ x,
                      const float* __restrict__ Wh,
                      const float* __restrict__ bh,
                      const float* __restrict__ Wz,
                      const float* __restrict__ bz)
{
    __shared__ float Xs[BK][BM];
    __shared__ float Zs[BK][BN];
    __shared__ float Hs[BK][BN];

    const int tid = threadIdx.x;
    const int tx  = tid & 15;    // n direction: 16 threads * 4 cols
    const int ty  = tid >> 4;    // m direction: 16 threads * 8 rows
    const int n0  = blockIdx.x * BN;
    const int m0  = blockIdx.y * BM;

    float accK[8][4];
    float accA[8][4];
    #pragma unroll
    for (int i = 0; i < 8; i++)
        #pragma unroll
        for (int j = 0; j < 4; j++) { accK[i][j] = 0.f; accA[i][j] = 0.f; }

    for (int k0 = 0; k0 < D_; k0 += BK) {
        // --- load x tile (128 x 16) as 512 float4s, 2 per thread, transpose ---
        #pragma unroll
        for (int l = 0; l < 2; l++) {
            int f   = tid + l * 256;
            int row = f >> 2;
            int kc  = (f & 3) * 4;
            float4 val = *reinterpret_cast<const float4*>(
                &x[(size_t)(m0 + row) * D_ + k0 + kc]);
            Xs[kc + 0][row] = val.x;
            Xs[kc + 1][row] = val.y;
            Xs[kc + 2][row] = val.z;
            Xs[kc + 3][row] = val.w;
        }
        // --- load W tiles (64 x 16) as 256 float4s, 1 per thread each ---
        {
            int n  = tid >> 2;
            int kc = (tid & 3) * 4;
            float4 vz = *reinterpret_cast<const float4*>(
                &Wz[(size_t)(n0 + n) * D_ + k0 + kc]);
            Zs[kc + 0][n] = vz.x; Zs[kc + 1][n] = vz.y;
            Zs[kc + 2][n] = vz.z; Zs[kc + 3][n] = vz.w;
            float4 vh = *reinterpret_cast<const float4*>(
                &Wh[(size_t)(n0 + n) * D_ + k0 + kc]);
            Hs[kc + 0][n] = vh.x; Hs[kc + 1][n] = vh.y;
            Hs[kc + 2][n] = vh.z; Hs[kc + 3][n] = vh.w;
        }
        __syncthreads();

        #pragma unroll
        for (int kk = 0; kk < BK; kk++) {
            float a[8], wz[4], wh[4];
            #pragma unroll
            for (int i = 0; i < 8; i++) a[i] = Xs[kk][ty * 8 + i];
            #pragma unroll
            for (int j = 0; j < 4; j++) { wz[j] = Zs[kk][tx * 4 + j]; wh[j] = Hs[kk][tx * 4 + j]; }
            #pragma unroll
            for (int i = 0; i < 8; i++)
                #pragma unroll
                for (int j = 0; j < 4; j++) {
                    accK[i][j] = fmaf(a[i], wz[j], accK[i][j]);
                    accA[i][j] = fmaf(a[i], wh[j], accA[i][j]);
                }
        }
        __syncthreads();
    }

    // --- epilogue: gates ---
    float bzv[4], bhv[4];
    #pragma unroll
    for (int j = 0; j < 4; j++) {
        bzv[j] = bz[n0 + tx * 4 + j];
        bhv[j] = bh[n0 + tx * 4 + j];
    }

    #pragma unroll
    for (int i = 0; i < 8; i++) {
        int m = m0 + ty * 8 + i;
        float4 c4, v4;
        float cc[4], vv[4];
        #pragma unroll
        for (int j = 0; j < 4; j++) {
            float k  = accK[i][j] + bzv[j];
            float aa = accA[i][j] + bhv[j];
            float c  = 1.f / (1.f + __expf(k));     // sigmoid(-k) = 1 - z
            float s  = 1.f / (1.f + __expf(-k));    // sigmoid(k)  = z
            float g  = (aa >= 0.f) ? (aa + 0.5f) : (1.f / (1.f + __expf(-aa)));
            cc[j] = c;
            vv[j] = s * g;
        }
        c4.x = cc[0]; c4.y = cc[1]; c4.z = cc[2]; c4.w = cc[3];
        v4.x = vv[0]; v4.y = vv[1]; v4.z = vv[2]; v4.w = vv[3];
        size_t off = (size_t)m * H_ + n0 + tx * 4;
        *reinterpret_cast<float4*>(&g_c[off]) = c4;
        *reinterpret_cast<float4*>(&g_v[off]) = v4;
    }
}

// ---------------------------------------------------------------------------
// Kernel 2: per-chunk affine summaries.  h_out = A * h_in + B  over TC steps.
// grid (NCHUNK, B), 512 threads (one per channel h). Coalesced along h.
// ---------------------------------------------------------------------------
__global__ void scan_pass1()
{
    const int h     = threadIdx.x;
    const int chunk = blockIdx.x;
    const int b     = blockIdx.y;
    size_t base = ((size_t)(b * T_ + chunk * TC)) * H_ + h;
    float A = 1.f, Bv = 0.f;
    #pragma unroll 4
    for (int t = 0; t < TC; t++) {
        float cc = g_c[base];
        float vv = g_v[base];
        Bv = fmaf(cc, Bv, vv);
        A *= cc;                 // underflow to 0 is mathematically benign
        base += H_;
    }
    int o = (b * NCHUNK + chunk) * H_ + h;
    g_sumA[o] = A;
    g_sumB[o] = Bv;
}

// ---------------------------------------------------------------------------
// Kernel 3: sequential combine over chunks -> carry-in per chunk.
// grid (B), 512 threads.
// ---------------------------------------------------------------------------
__global__ void scan_pass2(const float* __restrict__ h_prev)
{
    const int h = threadIdx.x;
    const int b = blockIdx.x;
    float carry = h_prev[b * H_ + h];
    #pragma unroll
    for (int j = 0; j < NCHUNK; j++) {
        int o = (b * NCHUNK + j) * H_ + h;
        g_carry[o] = carry;
        carry = fmaf(g_sumA[o], carry, g_sumB[o]);
    }
}

// ---------------------------------------------------------------------------
// Kernel 4: replay chunk scan with correct carry, write output.
// ---------------------------------------------------------------------------
__global__ void scan_pass3(float* __restrict__ out)
{
    const int h     = threadIdx.x;
    const int chunk = blockIdx.x;
    const int b     = blockIdx.y;
    float hc = g_carry[(b * NCHUNK + chunk) * H_ + h];
    size_t base = ((size_t)(b * T_ + chunk * TC)) * H_ + h;
    #pragma unroll 4
    for (int t = 0; t < TC; t++) {
        hc = fmaf(g_c[base], hc, g_v[base]);
        out[base] = hc;
        base += H_;
    }
}

// ---------------------------------------------------------------------------
extern "C" void kernel_launch(void* const* d_in, const int* in_sizes, int n_in,
                              void* d_out, int out_size)
{
    const float* x      = (const float*)d_in[0];  // (B,T,D)
    const float* h_prev = (const float*)d_in[1];  // (B,1,H)
    const float* W_h    = (const float*)d_in[2];  // (H,D)
    const float* b_h    = (const float*)d_in[3];  // (H)
    const float* W_z    = (const float*)d_in[4];  // (H,D)
    const float* b_z    = (const float*)d_in[5];  // (H)
    float* out = (float*)d_out;                   // (B,T,H)

    dim3 gemm_grid(H_ / BN, M_ / BM);             // (8, 256)
    gemm_gate_kernel<<<gemm_grid, 256>>>(x, W_h, b_h, W_z, b_z);

    scan_pass1<<<dim3(NCHUNK, B_), H_>>>();
    scan_pass2<<<B_, H_>>>(h_prev);
    scan_pass3<<<dim3(NCHUNK, B_), H_>>>(out);
}

// round 3
// speedup vs baseline: 1.7548x; 1.7548x over previous
#include <cuda_runtime.h>
#include <cuda_bf16.h>
#include <cstdint>

// Problem shapes (fixed by the dataset)
#define B_  4
#define T_  8192
#define D_  512
#define H_  512
#define M_  (B_ * T_)        // 32768 rows

#define NCHUNK 32
#define TC     (T_ / NCHUNK) // 256

// Scratch (device globals: allocation-free rule)
__device__ float g_c[(size_t)M_ * H_];               // 64 MB: coeff  = sigmoid(-k)
__device__ float g_v[(size_t)M_ * H_];               // 64 MB: value  = sigmoid(k) * g(a)
__device__ float g_sumA[B_ * NCHUNK * H_];
__device__ float g_sumB[B_ * NCHUNK * H_];
__device__ float g_carry[B_ * NCHUNK * H_];

// ---------------------------------------------------------------------------
// GEMM config: CTA tile M=128, N=64 (both outputs), K chunk 64, 16 warps.
// ---------------------------------------------------------------------------
#define BM 128
#define BN 64
#define KCH 64
#define NKC (D_ / KCH)       // 8

// smem stage layout (bytes). Rows padded to 72 bf16 = 144B (conflict-free ldmatrix).
#define OX_H 0               // x hi  : 128 x 144
#define OX_L 18432           // x lo
#define OW0H 36864           // Wz hi : 64 x 144
#define OW0L 46080           // Wz lo
#define OW1H 55296           // Wh hi
#define OW1L 64512           // Wh lo
#define SSTR 73728           // stage stride
#define SMEM_BYTES (2 * SSTR)   // 147456 (double buffered)

__device__ __forceinline__ uint32_t smem_u32(const void* p) {
    uint32_t a;
    asm("{ .reg .u64 t; cvta.to.shared.u64 t, %1; cvt.u32.u64 %0, t; }"
        : "=r"(a) : "l"(p));
    return a;
}

__device__ __forceinline__ void ldsm_x4(uint32_t* r, uint32_t addr) {
    asm volatile("ldmatrix.sync.aligned.m8n8.x4.shared.b16 {%0,%1,%2,%3}, [%4];"
                 : "=r"(r[0]), "=r"(r[1]), "=r"(r[2]), "=r"(r[3]) : "r"(addr));
}

__device__ __forceinline__ void mma_bf16(float* d, const uint32_t* a, const uint32_t* b) {
    asm volatile("mma.sync.aligned.m16n8k16.row.col.f32.bf16.bf16.f32 "
                 "{%0,%1,%2,%3}, {%4,%5,%6,%7}, {%8,%9}, {%0,%1,%2,%3};"
                 : "+f"(d[0]), "+f"(d[1]), "+f"(d[2]), "+f"(d[3])
                 : "r"(a[0]), "r"(a[1]), "r"(a[2]), "r"(a[3]), "r"(b[0]), "r"(b[1]));
}

struct Pref { float4 x[4]; float4 wz[2]; float4 wh[2]; };

__device__ __forceinline__ void gload(Pref& p, const float* __restrict__ x,
                                      const float* __restrict__ Wz,
                                      const float* __restrict__ Wh,
                                      int m0, int n0, int k0, int tid) {
    #pragma unroll
    for (int i = 0; i < 4; i++) {
        int f = tid + i * 512, row = f >> 4, c4 = (f & 15) * 4;
        p.x[i] = *reinterpret_cast<const float4*>(&x[(size_t)(m0 + row) * D_ + k0 + c4]);
    }
    #pragma unroll
    for (int i = 0; i < 2; i++) {
        int f = tid + i * 512, row = f >> 4, c4 = (f & 15) * 4;
        p.wz[i] = *reinterpret_cast<const float4*>(&Wz[(size_t)(n0 + row) * D_ + k0 + c4]);
        p.wh[i] = *reinterpret_cast<const float4*>(&Wh[(size_t)(n0 + row) * D_ + k0 + c4]);
    }
}

__device__ __forceinline__ void split_store(char* hp, char* lp, float4 v) {
    __nv_bfloat16 hx = __float2bfloat16(v.x), hy = __float2bfloat16(v.y);
    __nv_bfloat16 hz = __float2bfloat16(v.z), hw = __float2bfloat16(v.w);
    __nv_bfloat162 h0{hx, hy}, h1{hz, hw};
    __nv_bfloat162 l0{__float2bfloat16(v.x - __bfloat162float(hx)),
                      __float2bfloat16(v.y - __bfloat162float(hy))};
    __nv_bfloat162 l1{__float2bfloat16(v.z - __bfloat162float(hz)),
                      __float2bfloat16(v.w - __bfloat162float(hw))};
    uint2 hu{*reinterpret_cast<uint32_t*>(&h0), *reinterpret_cast<uint32_t*>(&h1)};
    uint2 lu{*reinterpret_cast<uint32_t*>(&l0), *reinterpret_cast<uint32_t*>(&l1)};
    *reinterpret_cast<uint2*>(hp) = hu;
    *reinterpret_cast<uint2*>(lp) = lu;
}

__device__ __forceinline__ void sstore(const Pref& p, char* sb, int tid) {
    #pragma unroll
    for (int i = 0; i < 4; i++) {
        int f = tid + i * 512, row = f >> 4, c4 = (f & 15) * 4;
        int off = row * 144 + c4 * 2;
        split_store(sb + OX_H + off, sb + OX_L + off, p.x[i]);
    }
    #pragma unroll
    for (int i = 0; i < 2; i++) {
        int f = tid + i * 512, row = f >> 4, c4 = (f & 15) * 4;
        int off = row * 144 + c4 * 2;
        split_store(sb + OW0H + off, sb + OW0L + off, p.wz[i]);
        split_store(sb + OW1H + off, sb + OW1L + off, p.wh[i]);
    }
}

__device__ __forceinline__ void gate(float k, float a, float& c, float& v) {
    c = 1.f / (1.f + __expf(k));                                 // sigmoid(-k)
    float s = 1.f / (1.f + __expf(-k));                          // sigmoid(k)
    float g = (a >= 0.f) ? (a + 0.5f) : (1.f / (1.f + __expf(-a)));
    v = s * g;
}

// ---------------------------------------------------------------------------
// Kernel 1: split-bf16 mma.sync dual GEMM + gate epilogue.
//   warps 0-7  : accK = x*Wz^T   (warp tile 32x32)
//   warps 8-15 : accA = x*Wh^T
// ---------------------------------------------------------------------------
__global__ __launch_bounds__(512, 1)
void gemm_gate_mma(const float* __restrict__ x,
                   const float* __restrict__ Wh,
                   const float* __restrict__ bh,
                   const float* __restrict__ Wz,
                   const float* __restrict__ bz)
{
    extern __shared__ char smem[];
    const int tid  = threadIdx.x;
    const int wid  = tid >> 5;
    const int lane = tid & 31;
    const int n0   = blockIdx.x * BN;
    const int m0   = blockIdx.y * BM;
    const int out  = wid >> 3;          // 0: accK(Wz), 1: accA(Wh)
    const int wm   = (wid >> 1) & 3;    // m warp tile (32 rows)
    const int wn   = wid & 1;           // n warp tile (32 cols)

    float acc[32];
    #pragma unroll
    for (int i = 0; i < 32; i++) acc[i] = 0.f;

    const uint32_t sm0 = smem_u32(smem);
    // A (x) ldmatrix lane addresses: row = wm*32 + ms*16 + (lane&15), kcol = (lane>>4)*8
    const uint32_t aHi = sm0 + OX_H + (uint32_t)(wm * 32 + (lane & 15)) * 144 + (lane >> 4) * 16;
    const uint32_t aLo = aHi + (OX_L - OX_H);
    // B (W) ldmatrix lane addresses: nrow = wn*32 + (lane>>4)*8 + (lane&7), kcol = ((lane>>3)&1)*8
    const uint32_t wH  = out ? OW1H : OW0H;
    const uint32_t bHi = sm0 + wH + (uint32_t)(wn * 32 + ((lane >> 4) << 3) + (lane & 7)) * 144
                         + ((lane >> 3) & 1) * 16;
    const uint32_t bLo = bHi + 9216;    // W?L - W?H

    Pref p;
    gload(p, x, Wz, Wh, m0, n0, 0, tid);
    sstore(p, smem, tid);
    __syncthreads();

    for (int kc = 0; kc < NKC; kc++) {
        if (kc + 1 < NKC) gload(p, x, Wz, Wh, m0, n0, (kc + 1) * KCH, tid);

        const uint32_t ss = (uint32_t)(kc & 1) * SSTR;
        #pragma unroll
        for (int kk = 0; kk < 4; kk++) {
            uint32_t ah[2][4], al[2][4], bhf[2][4], blf[2][4];
            #pragma unroll
            for (int ms = 0; ms < 2; ms++) {
                ldsm_x4(ah[ms], aHi + ss + ms * 2304 + kk * 32);
                ldsm_x4(al[ms], aLo + ss + ms * 2304 + kk * 32);
            }
            #pragma unroll
            for (int i = 0; i < 2; i++) {
                ldsm_x4(bhf[i], bHi + ss + i * 2304 + kk * 32);
                ldsm_x4(blf[i], bLo + ss + i * 2304 + kk * 32);
            }
            #pragma unroll
            for (int ms = 0; ms < 2; ms++)
                #pragma unroll
                for (int ns = 0; ns < 4; ns++) {
                    float* d = acc + (ms * 4 + ns) * 4;
                    const uint32_t* b_h = &bhf[ns >> 1][(ns & 1) * 2];
                    const uint32_t* b_l = &blf[ns >> 1][(ns & 1) * 2];
                    mma_bf16(d, ah[ms], b_h);   // hi * hi
                    mma_bf16(d, al[ms], b_h);   // lo * hi
                    mma_bf16(d, ah[ms], b_l);   // hi * lo
                }
        }

        if (kc + 1 < NKC) sstore(p, smem + (size_t)((kc + 1) & 1) * SSTR, tid);
        __syncthreads();
    }

    // ---- epilogue: accA warps stage to smem, accK warps fuse gates ----
    float* Cs = reinterpret_cast<float*>(smem);   // [128][66] fp32, reuses stage 0
    if (out == 1) {
        #pragma unroll
        for (int ms = 0; ms < 2; ms++)
            #pragma unroll
            for (int ns = 0; ns < 4; ns++) {
                float* d = acc + (ms * 4 + ns) * 4;
                int ml = wm * 32 + ms * 16 + (lane >> 2);
                int nl = wn * 32 + ns * 8 + (lane & 3) * 2;
                *reinterpret_cast<float2*>(&Cs[ml * 66 + nl])       = make_float2(d[0], d[1]);
                *reinterpret_cast<float2*>(&Cs[(ml + 8) * 66 + nl]) = make_float2(d[2], d[3]);
            }
    }
    __syncthreads();
    if (out == 0) {
        #pragma unroll
        for (int ms = 0; ms < 2; ms++)
            #pragma unroll
            for (int ns = 0; ns < 4; ns++) {
                float* d = acc + (ms * 4 + ns) * 4;
                int ml = wm * 32 + ms * 16 + (lane >> 2);
                int nl = wn * 32 + ns * 8 + (lane & 3) * 2;
                int ng = n0 + nl;
                float bz0 = bz[ng], bz1 = bz[ng + 1];
                float bh0 = bh[ng], bh1 = bh[ng + 1];
                #pragma unroll
                for (int rh = 0; rh < 2; rh++) {
                    int m = m0 + ml + rh * 8;
                    float2 aa = *reinterpret_cast<float2*>(&Cs[(ml + rh * 8) * 66 + nl]);
                    float c0, v0, c1, v1;
                    gate(d[rh * 2 + 0] + bz0, aa.x + bh0, c0, v0);
                    gate(d[rh * 2 + 1] + bz1, aa.y + bh1, c1, v1);
                    size_t o = (size_t)m * H_ + ng;
                    *reinterpret_cast<float2*>(&g_c[o]) = make_float2(c0, c1);
                    *reinterpret_cast<float2*>(&g_v[o]) = make_float2(v0, v1);
                }
            }
    }
}

// ---------------------------------------------------------------------------
// Kernel 2: per-chunk affine summaries.  h_out = A * h_in + B  over TC steps.
// ---------------------------------------------------------------------------
__global__ void scan_pass1()
{
    const int h     = threadIdx.x;
    const int chunk = blockIdx.x;
    const int b     = blockIdx.y;
    size_t base = ((size_t)(b * T_ + chunk * TC)) * H_ + h;
    float A = 1.f, Bv = 0.f;
    #pragma unroll 4
    for (int t = 0; t < TC; t++) {
        float cc = g_c[base];
        float vv = g_v[base];
        Bv = fmaf(cc, Bv, vv);
        A *= cc;
        base += H_;
    }
    int o = (b * NCHUNK + chunk) * H_ + h;
    g_sumA[o] = A;
    g_sumB[o] = Bv;
}

// ---------------------------------------------------------------------------
// Kernel 3: sequential combine over chunks -> carry-in per chunk.
// ---------------------------------------------------------------------------
__global__ void scan_pass2(const float* __restrict__ h_prev)
{
    const int h = threadIdx.x;
    const int b = blockIdx.x;
    float carry = h_prev[b * H_ + h];
    #pragma unroll
    for (int j = 0; j < NCHUNK; j++) {
        int o = (b * NCHUNK + j) * H_ + h;
        g_carry[o] = carry;
        carry = fmaf(g_sumA[o], carry, g_sumB[o]);
    }
}

// ---------------------------------------------------------------------------
// Kernel 4: replay chunk scan with correct carry, write output.
// ---------------------------------------------------------------------------
__global__ void scan_pass3(float* __restrict__ out)
{
    const int h     = threadIdx.x;
    const int chunk = blockIdx.x;
    const int b     = blockIdx.y;
    float hc = g_carry[(b * NCHUNK + chunk) * H_ + h];
    size_t base = ((size_t)(b * T_ + chunk * TC)) * H_ + h;
    #pragma unroll 4
    for (int t = 0; t < TC; t++) {
        hc = fmaf(g_c[base], hc, g_v[base]);
        out[base] = hc;
        base += H_;
    }
}

// ---------------------------------------------------------------------------
extern "C" void kernel_launch(void* const* d_in, const int* in_sizes, int n_in,
                              void* d_out, int out_size)
{
    const float* x      = (const float*)d_in[0];  // (B,T,D)
    const float* h_prev = (const float*)d_in[1];  // (B,1,H)
    const float* W_h    = (const float*)d_in[2];  // (H,D)
    const float* b_h    = (const float*)d_in[3];  // (H)
    const float* W_z    = (const float*)d_in[4];  // (H,D)
    const float* b_z    = (const float*)d_in[5];  // (H)
    float* out = (float*)d_out;                   // (B,T,H)

    cudaFuncSetAttribute(gemm_gate_mma, cudaFuncAttributeMaxDynamicSharedMemorySize, SMEM_BYTES);

    dim3 gemm_grid(H_ / BN, M_ / BM);             // (8, 256)
    gemm_gate_mma<<<gemm_grid, 512, SMEM_BYTES>>>(x, W_h, b_h, W_z, b_z);

    scan_pass1<<<dim3(NCHUNK, B_), H_>>>();
    scan_pass2<<<B_, H_>>>(h_prev);
    scan_pass3<<<dim3(NCHUNK, B_), H_>>>(out);
}

// round 4
// speedup vs baseline: 1.7597x; 1.0028x over previous
#include <cuda_runtime.h>
#include <cuda_bf16.h>
#include <cstdint>

// Problem shapes (fixed by the dataset)
#define B_  4
#define T_  8192
#define D_  512
#define H_  512
#define M_  (B_ * T_)        // 32768 rows

#define NCHUNK 64
#define TC     (T_ / NCHUNK) // 128

// Scratch (device globals: allocation-free rule)
__device__ float g_c[(size_t)M_ * H_];               // 64 MB: coeff  = sigmoid(-k)
__device__ float g_v[(size_t)M_ * H_];               // 64 MB: value  = sigmoid(k) * g(a)
__device__ float g_sumA[B_ * NCHUNK * H_];
__device__ float g_sumB[B_ * NCHUNK * H_];
__device__ float g_carry[B_ * NCHUNK * H_];

// Pre-split bf16 operands
__device__ __nv_bfloat16 g_xh[(size_t)M_ * D_];      // 32 MB
__device__ __nv_bfloat16 g_xl[(size_t)M_ * D_];      // 32 MB
__device__ __nv_bfloat16 g_wzh[H_ * D_];
__device__ __nv_bfloat16 g_wzl[H_ * D_];
__device__ __nv_bfloat16 g_whh[H_ * D_];
__device__ __nv_bfloat16 g_whl[H_ * D_];

// ---------------------------------------------------------------------------
// GEMM config: CTA tile M=128, N=64 (both outputs), K chunk 64, 16 warps.
// ---------------------------------------------------------------------------
#define BM 128
#define BN 64
#define KCH 64
#define NKC (D_ / KCH)       // 8

// smem stage layout (bytes). Rows padded to 72 bf16 = 144B (conflict-free ldmatrix).
#define OX_H 0               // x hi  : 128 x 144
#define OX_L 18432           // x lo
#define OW0H 36864           // Wz hi : 64 x 144
#define OW0L 46080           // Wz lo
#define OW1H 55296           // Wh hi
#define OW1L 64512           // Wh lo
#define SSTR 73728           // stage stride
#define SMEM_BYTES (2 * SSTR)   // 147456 (double buffered)

__device__ __forceinline__ uint32_t smem_u32(const void* p) {
    uint32_t a;
    asm("{ .reg .u64 t; cvta.to.shared.u64 t, %1; cvt.u32.u64 %0, t; }"
        : "=r"(a) : "l"(p));
    return a;
}

#define CP16(dst, src) \
    asm volatile("cp.async.cg.shared.global [%0], [%1], 16;" :: "r"(dst), "l"(src))
#define CP_COMMIT() asm volatile("cp.async.commit_group;" ::: "memory")
#define CP_WAIT(n)  asm volatile("cp.async.wait_group %0;" :: "n"(n) : "memory")

__device__ __forceinline__ void ldsm_x4(uint32_t* r, uint32_t addr) {
    asm volatile("ldmatrix.sync.aligned.m8n8.x4.shared.b16 {%0,%1,%2,%3}, [%4];"
                 : "=r"(r[0]), "=r"(r[1]), "=r"(r[2]), "=r"(r[3]) : "r"(addr));
}

__device__ __forceinline__ void mma_bf16(float* d, const uint32_t* a, const uint32_t* b) {
    asm volatile("mma.sync.aligned.m16n8k16.row.col.f32.bf16.bf16.f32 "
                 "{%0,%1,%2,%3}, {%4,%5,%6,%7}, {%8,%9}, {%0,%1,%2,%3};"
                 : "+f"(d[0]), "+f"(d[1]), "+f"(d[2]), "+f"(d[3])
                 : "r"(a[0]), "r"(a[1]), "r"(a[2]), "r"(a[3]), "r"(b[0]), "r"(b[1]));
}

__device__ __forceinline__ void gate(float k, float a, float& c, float& v) {
    c = 1.f / (1.f + __expf(k));                                 // sigmoid(-k)
    float s = 1.f / (1.f + __expf(-k));                          // sigmoid(k)
    float g = (a >= 0.f) ? (a + 0.5f) : (1.f / (1.f + __expf(-a)));
    v = s * g;
}

// ---------------------------------------------------------------------------
// Kernel 0a: split x into bf16 hi/lo.
// ---------------------------------------------------------------------------
__global__ __launch_bounds__(256)
void split_x(const float* __restrict__ x)
{
    size_t i = ((size_t)blockIdx.x * 256 + threadIdx.x) * 4;
    float4 v = *reinterpret_cast<const float4*>(&x[i]);
    __nv_bfloat16 hx = __float2bfloat16(v.x), hy = __float2bfloat16(v.y);
    __nv_bfloat16 hz = __float2bfloat16(v.z), hw = __float2bfloat16(v.w);
    __nv_bfloat162 h0{hx, hy}, h1{hz, hw};
    __nv_bfloat162 l0{__float2bfloat16(v.x - __bfloat162float(hx)),
                      __float2bfloat16(v.y - __bfloat162float(hy))};
    __nv_bfloat162 l1{__float2bfloat16(v.z - __bfloat162float(hz)),
                      __float2bfloat16(v.w - __bfloat162float(hw))};
    uint2 hu{*reinterpret_cast<uint32_t*>(&h0), *reinterpret_cast<uint32_t*>(&h1)};
    uint2 lu{*reinterpret_cast<uint32_t*>(&l0), *reinterpret_cast<uint32_t*>(&l1)};
    *reinterpret_cast<uint2*>(&g_xh[i]) = hu;
    *reinterpret_cast<uint2*>(&g_xl[i]) = lu;
}

// ---------------------------------------------------------------------------
// Kernel 0b: split Wz / Wh into bf16 hi/lo.
// ---------------------------------------------------------------------------
__global__ __launch_bounds__(256)
void split_w(const float* __restrict__ Wz, const float* __restrict__ Wh)
{
    size_t i = ((size_t)blockIdx.x * 256 + threadIdx.x) * 4;
    {
        float4 v = *reinterpret_cast<const float4*>(&Wz[i]);
        __nv_bfloat16 hx = __float2bfloat16(v.x), hy = __float2bfloat16(v.y);
        __nv_bfloat16 hz = __float2bfloat16(v.z), hw = __float2bfloat16(v.w);
        __nv_bfloat162 h0{hx, hy}, h1{hz, hw};
        __nv_bfloat162 l0{__float2bfloat16(v.x - __bfloat162float(hx)),
                          __float2bfloat16(v.y - __bfloat162float(hy))};
        __nv_bfloat162 l1{__float2bfloat16(v.z - __bfloat162float(hz)),
                          __float2bfloat16(v.w - __bfloat162float(hw))};
        uint2 hu{*reinterpret_cast<uint32_t*>(&h0), *reinterpret_cast<uint32_t*>(&h1)};
        uint2 lu{*reinterpret_cast<uint32_t*>(&l0), *reinterpret_cast<uint32_t*>(&l1)};
        *reinterpret_cast<uint2*>(&g_wzh[i]) = hu;
        *reinterpret_cast<uint2*>(&g_wzl[i]) = lu;
    }
    {
        float4 v = *reinterpret_cast<const float4*>(&Wh[i]);
        __nv_bfloat16 hx = __float2bfloat16(v.x), hy = __float2bfloat16(v.y);
        __nv_bfloat16 hz = __float2bfloat16(v.z), hw = __float2bfloat16(v.w);
        __nv_bfloat162 h0{hx, hy}, h1{hz, hw};
        __nv_bfloat162 l0{__float2bfloat16(v.x - __bfloat162float(hx)),
                          __float2bfloat16(v.y - __bfloat162float(hy))};
        __nv_bfloat162 l1{__float2bfloat16(v.z - __bfloat162float(hz)),
                          __float2bfloat16(v.w - __bfloat162float(hw))};
        uint2 hu{*reinterpret_cast<uint32_t*>(&h0), *reinterpret_cast<uint32_t*>(&h1)};
        uint2 lu{*reinterpret_cast<uint32_t*>(&l0), *reinterpret_cast<uint32_t*>(&l1)};
        *reinterpret_cast<uint2*>(&g_whh[i]) = hu;
        *reinterpret_cast<uint2*>(&g_whl[i]) = lu;
    }
}

// ---------------------------------------------------------------------------
// cp.async one K-chunk stage into smem buffer.
// ---------------------------------------------------------------------------
__device__ __forceinline__ void copy_stage(char* sb, int m0, int n0, int k0, int tid)
{
    const uint32_t sa = smem_u32(sb);
    // x hi/lo: 128 rows x 128B, 1024 x 16B each -> 2 per thread per matrix
    #pragma unroll
    for (int i = 0; i < 2; i++) {
        int f = tid + i * 512;
        int row = f >> 3, c = f & 7;
        uint32_t d = sa + row * 144 + c * 16;
        size_t   s = (size_t)(m0 + row) * D_ + k0 + c * 8;
        CP16(d + OX_H, &g_xh[s]);
        CP16(d + OX_L, &g_xl[s]);
    }
    // W tiles: 64 rows x 128B, 512 x 16B each -> 1 per thread per matrix
    {
        int row = tid >> 3, c = tid & 7;
        uint32_t d = sa + row * 144 + c * 16;
        size_t   s = (size_t)(n0 + row) * D_ + k0 + c * 8;
        CP16(d + OW0H, &g_wzh[s]);
        CP16(d + OW0L, &g_wzl[s]);
        CP16(d + OW1H, &g_whh[s]);
        CP16(d + OW1L, &g_whl[s]);
    }
}

// ---------------------------------------------------------------------------
// Kernel 1: split-bf16 mma.sync dual GEMM + gate epilogue.
//   warps 0-7  : accK = x*Wz^T   (warp tile 32x32)
//   warps 8-15 : accA = x*Wh^T
// ---------------------------------------------------------------------------
__global__ __launch_bounds__(512, 1)
void gemm_gate_mma(const float* __restrict__ bh, const float* __restrict__ bz)
{
    extern __shared__ char smem[];
    const int tid  = threadIdx.x;
    const int wid  = tid >> 5;
    const int lane = tid & 31;
    const int n0   = blockIdx.x * BN;
    const int m0   = blockIdx.y * BM;
    const int out  = wid >> 3;          // 0: accK(Wz), 1: accA(Wh)
    const int wm   = (wid >> 1) & 3;    // m warp tile (32 rows)
    const int wn   = wid & 1;           // n warp tile (32 cols)

    float acc[32];
    #pragma unroll
    for (int i = 0; i < 32; i++) acc[i] = 0.f;

    const uint32_t sm0 = smem_u32(smem);
    // A (x) ldmatrix lane addresses: row = wm*32 + ms*16 + (lane&15), kcol = (lane>>4)*8
    const uint32_t aHi = sm0 + OX_H + (uint32_t)(wm * 32 + (lane & 15)) * 144 + (lane >> 4) * 16;
    const uint32_t aLo = aHi + (OX_L - OX_H);
    // B (W) ldmatrix lane addresses: nrow = wn*32 + (lane>>4)*8 + (lane&7), kcol = ((lane>>3)&1)*8
    const uint32_t wH  = out ? OW1H : OW0H;
    const uint32_t bHi = sm0 + wH + (uint32_t)(wn * 32 + ((lane >> 4) << 3) + (lane & 7)) * 144
                         + ((lane >> 3) & 1) * 16;
    const uint32_t bLo = bHi + 9216;    // W?L - W?H

    copy_stage(smem, m0, n0, 0, tid);
    CP_COMMIT();

    for (int kc = 0; kc < NKC; kc++) {
        if (kc + 1 < NKC) {
            copy_stage(smem + (size_t)((kc + 1) & 1) * SSTR, m0, n0, (kc + 1) * KCH, tid);
            CP_COMMIT();
            CP_WAIT(1);
        } else {
            CP_WAIT(0);
        }
        __syncthreads();

        const uint32_t ss = (uint32_t)(kc & 1) * SSTR;
        #pragma unroll
        for (int kk = 0; kk < 4; kk++) {
            uint32_t ah[2][4], al[2][4], bhf[2][4], blf[2][4];
            #pragma unroll
            for (int ms = 0; ms < 2; ms++) {
                ldsm_x4(ah[ms], aHi + ss + ms * 2304 + kk * 32);
                ldsm_x4(al[ms], aLo + ss + ms * 2304 + kk * 32);
            }
            #pragma unroll
            for (int i = 0; i < 2; i++) {
                ldsm_x4(bhf[i], bHi + ss + i * 2304 + kk * 32);
                ldsm_x4(blf[i], bLo + ss + i * 2304 + kk * 32);
            }
            #pragma unroll
            for (int ms = 0; ms < 2; ms++)
                #pragma unroll
                for (int ns = 0; ns < 4; ns++) {
                    float* d = acc + (ms * 4 + ns) * 4;
                    const uint32_t* b_h = &bhf[ns >> 1][(ns & 1) * 2];
                    const uint32_t* b_l = &blf[ns >> 1][(ns & 1) * 2];
                    mma_bf16(d, ah[ms], b_h);   // hi * hi
                    mma_bf16(d, al[ms], b_h);   // lo * hi
                    mma_bf16(d, ah[ms], b_l);   // hi * lo
                }
        }
        __syncthreads();
    }

    // ---- epilogue: accA warps stage to smem, accK warps fuse gates ----
    float* Cs = reinterpret_cast<float*>(smem);   // [128][66] fp32, reuses stage 0
    if (out == 1) {
        #pragma unroll
        for (int ms = 0; ms < 2; ms++)
            #pragma unroll
            for (int ns = 0; ns < 4; ns++) {
                float* d = acc + (ms * 4 + ns) * 4;
                int ml = wm * 32 + ms * 16 + (lane >> 2);
                int nl = wn * 32 + ns * 8 + (lane & 3) * 2;
                *reinterpret_cast<float2*>(&Cs[ml * 66 + nl])       = make_float2(d[0], d[1]);
                *reinterpret_cast<float2*>(&Cs[(ml + 8) * 66 + nl]) = make_float2(d[2], d[3]);
            }
    }
    __syncthreads();
    if (out == 0) {
        #pragma unroll
        for (int ms = 0; ms < 2; ms++)
            #pragma unroll
            for (int ns = 0; ns < 4; ns++) {
                float* d = acc + (ms * 4 + ns) * 4;
                int ml = wm * 32 + ms * 16 + (lane >> 2);
                int nl = wn * 32 + ns * 8 + (lane & 3) * 2;
                int ng = n0 + nl;
                float bz0 = bz[ng], bz1 = bz[ng + 1];
                float bh0 = bh[ng], bh1 = bh[ng + 1];
                #pragma unroll
                for (int rh = 0; rh < 2; rh++) {
                    int m = m0 + ml + rh * 8;
                    float2 aa = *reinterpret_cast<float2*>(&Cs[(ml + rh * 8) * 66 + nl]);
                    float c0, v0, c1, v1;
                    gate(d[rh * 2 + 0] + bz0, aa.x + bh0, c0, v0);
                    gate(d[rh * 2 + 1] + bz1, aa.y + bh1, c1, v1);
                    size_t o = (size_t)m * H_ + ng;
                    *reinterpret_cast<float2*>(&g_c[o]) = make_float2(c0, c1);
                    *reinterpret_cast<float2*>(&g_v[o]) = make_float2(v0, v1);
                }
            }
    }
}

// ---------------------------------------------------------------------------
// Kernel 2: per-chunk affine summaries.  h_out = A * h_in + B  over TC steps.
// ---------------------------------------------------------------------------
__global__ void scan_pass1()
{
    const int h     = threadIdx.x;
    const int chunk = blockIdx.x;
    const int b     = blockIdx.y;
    size_t base = ((size_t)(b * T_ + chunk * TC)) * H_ + h;
    float A = 1.f, Bv = 0.f;
    #pragma unroll 4
    for (int t = 0; t < TC; t++) {
        float cc = g_c[base];
        float vv = g_v[base];
        Bv = fmaf(cc, Bv, vv);
        A *= cc;
        base += H_;
    }
    int o = (b * NCHUNK + chunk) * H_ + h;
    g_sumA[o] = A;
    g_sumB[o] = Bv;
}

// ---------------------------------------------------------------------------
// Kernel 3: sequential combine over chunks -> carry-in per chunk.
// ---------------------------------------------------------------------------
__global__ void scan_pass2(const float* __restrict__ h_prev)
{
    const int h = threadIdx.x;
    const int b = blockIdx.x;
    float carry = h_prev[b * H_ + h];
    #pragma unroll
    for (int j = 0; j < NCHUNK; j++) {
        int o = (b * NCHUNK + j) * H_ + h;
        g_carry[o] = carry;
        carry = fmaf(g_sumA[o], carry, g_sumB[o]);
    }
}

// ---------------------------------------------------------------------------
// Kernel 4: replay chunk scan with correct carry, write output.
// ---------------------------------------------------------------------------
__global__ void scan_pass3(float* __restrict__ out)
{
    const int h     = threadIdx.x;
    const int chunk = blockIdx.x;
    const int b     = blockIdx.y;
    float hc = g_carry[(b * NCHUNK + chunk) * H_ + h];
    size_t base = ((size_t)(b * T_ + chunk * TC)) * H_ + h;
    #pragma unroll 4
    for (int t = 0; t < TC; t++) {
        hc = fmaf(g_c[base], hc, g_v[base]);
        out[base] = hc;
        base += H_;
    }
}

// ---------------------------------------------------------------------------
extern "C" void kernel_launch(void* const* d_in, const int* in_sizes, int n_in,
                              void* d_out, int out_size)
{
    const float* x      = (const float*)d_in[0];  // (B,T,D)
    const float* h_prev = (const float*)d_in[1];  // (B,1,H)
    const float* W_h    = (const float*)d_in[2];  // (H,D)
    const float* b_h    = (const float*)d_in[3];  // (H)
    const float* W_z    = (const float*)d_in[4];  // (H,D)
    const float* b_z    = (const float*)d_in[5];  // (H)
    float* out = (float*)d_out;                   // (B,T,H)

    cudaFuncSetAttribute(gemm_gate_mma, cudaFuncAttributeMaxDynamicSharedMemorySize, SMEM_BYTES);

    split_x<<<(M_ * D_) / (256 * 4), 256>>>(x);
    split_w<<<(H_ * D_) / (256 * 4), 256>>>(W_z, W_h);

    dim3 gemm_grid(H_ / BN, M_ / BM);             // (8, 256)
    gemm_gate_mma<<<gemm_grid, 512, SMEM_BYTES>>>(b_h, b_z);

    scan_pass1<<<dim3(NCHUNK, B_), H_>>>();
    scan_pass2<<<B_, H_>>>(h_prev);
    scan_pass3<<<dim3(NCHUNK, B_), H_>>>(out);
}

// round 6
// speedup vs baseline: 2.1450x; 1.2189x over previous
#include <cuda_runtime.h>
#include <cuda_bf16.h>
#include <cstdint>

// Problem shapes (fixed by the dataset)
#define B_  4
#define T_  8192
#define D_  512
#define H_  512
#define M_  (B_ * T_)        // 32768 rows

#define NCHUNK 64
#define TC     (T_ / NCHUNK) // 128

// Scratch (device globals: allocation-free rule)
__device__ float g_c[(size_t)M_ * H_];               // 64 MB: coeff  = sigmoid(-k)
__device__ float g_v[(size_t)M_ * H_];               // 64 MB: value  = sigmoid(k) * g(a)
__device__ float g_sumA[B_ * NCHUNK * H_];
__device__ float g_sumB[B_ * NCHUNK * H_];
__device__ float g_carry[B_ * NCHUNK * H_];

// Pre-split bf16 operands
__device__ __nv_bfloat16 g_xh[(size_t)M_ * D_];      // 32 MB
__device__ __nv_bfloat16 g_xl[(size_t)M_ * D_];      // 32 MB
__device__ __nv_bfloat16 g_wzh[H_ * D_];
__device__ __nv_bfloat16 g_wzl[H_ * D_];
__device__ __nv_bfloat16 g_whh[H_ * D_];
__device__ __nv_bfloat16 g_whl[H_ * D_];

// ---------------------------------------------------------------------------
// GEMM config: CTA tile M=128, N=64, K chunk 32, 8 dual-output warps.
// ---------------------------------------------------------------------------
#define BM 128
#define BN 64
#define KCH 32
#define NKC (D_ / KCH)       // 16
#define NSTAGE 2

// Stage layout (bytes). Row stride 80 = 64B data + 16B pad:
//  - multiple of 16 -> cp.async/ldmatrix alignment OK
//  - 80*r mod 128, r=0..7 -> {0,80,32,112,64,16,96,48}: conflict-free ldmatrix.
#define RS   80
#define OX_H 0                     // x hi : 128 x 80
#define OX_L (OX_H + BM * RS)      // 10240
#define OW0H (OX_L + BM * RS)      // 20480  Wz hi : 64 x 80
#define OW0L (OW0H + BN * RS)      // 25600
#define OW1H (OW0L + BN * RS)      // 30720  Wh hi
#define OW1L (OW1H + BN * RS)      // 35840
#define SSTR (OW1L + BN * RS)      // 40960
#define SMEM_BYTES (NSTAGE * SSTR) // 81920

__device__ __forceinline__ uint32_t smem_u32(const void* p) {
    uint32_t a;
    asm("{ .reg .u64 t; cvta.to.shared.u64 t, %1; cvt.u32.u64 %0, t; }"
        : "=r"(a) : "l"(p));
    return a;
}

#define CP16(dst, src) \
    asm volatile("cp.async.cg.shared.global [%0], [%1], 16;" :: "r"(dst), "l"(src))
#define CP_COMMIT() asm volatile("cp.async.commit_group;" ::: "memory")
#define CP_WAIT(n)  asm volatile("cp.async.wait_group %0;" :: "n"(n) : "memory")

__device__ __forceinline__ void ldsm_x4(uint32_t* r, uint32_t addr) {
    asm volatile("ldmatrix.sync.aligned.m8n8.x4.shared.b16 {%0,%1,%2,%3}, [%4];"
                 : "=r"(r[0]), "=r"(r[1]), "=r"(r[2]), "=r"(r[3]) : "r"(addr));
}

__device__ __forceinline__ void mma_bf16(float* d, const uint32_t* a, const uint32_t* b) {
    asm volatile("mma.sync.aligned.m16n8k16.row.col.f32.bf16.bf16.f32 "
                 "{%0,%1,%2,%3}, {%4,%5,%6,%7}, {%8,%9}, {%0,%1,%2,%3};"
                 : "+f"(d[0]), "+f"(d[1]), "+f"(d[2]), "+f"(d[3])
                 : "r"(a[0]), "r"(a[1]), "r"(a[2]), "r"(a[3]), "r"(b[0]), "r"(b[1]));
}

__device__ __forceinline__ void gate(float k, float a, float& c, float& v) {
    c = 1.f / (1.f + __expf(k));                                 // sigmoid(-k)
    float s = 1.f / (1.f + __expf(-k));                          // sigmoid(k)
    float g = (a >= 0.f) ? (a + 0.5f) : (1.f / (1.f + __expf(-a)));
    v = s * g;
}

// ---------------------------------------------------------------------------
// Kernel 0a/0b: split fp32 into bf16 hi/lo.
// ---------------------------------------------------------------------------
__device__ __forceinline__ void split4(float4 v, uint2& hu, uint2& lu) {
    __nv_bfloat16 hx = __float2bfloat16(v.x), hy = __float2bfloat16(v.y);
    __nv_bfloat16 hz = __float2bfloat16(v.z), hw = __float2bfloat16(v.w);
    __nv_bfloat162 h0{hx, hy}, h1{hz, hw};
    __nv_bfloat162 l0{__float2bfloat16(v.x - __bfloat162float(hx)),
                      __float2bfloat16(v.y - __bfloat162float(hy))};
    __nv_bfloat162 l1{__float2bfloat16(v.z - __bfloat162float(hz)),
                      __float2bfloat16(v.w - __bfloat162float(hw))};
    hu = uint2{*reinterpret_cast<uint32_t*>(&h0), *reinterpret_cast<uint32_t*>(&h1)};
    lu = uint2{*reinterpret_cast<uint32_t*>(&l0), *reinterpret_cast<uint32_t*>(&l1)};
}

__global__ __launch_bounds__(256)
void split_x(const float* __restrict__ x)
{
    size_t i = ((size_t)blockIdx.x * 256 + threadIdx.x) * 4;
    uint2 hu, lu;
    split4(*reinterpret_cast<const float4*>(&x[i]), hu, lu);
    *reinterpret_cast<uint2*>(&g_xh[i]) = hu;
    *reinterpret_cast<uint2*>(&g_xl[i]) = lu;
}

__global__ __launch_bounds__(256)
void split_w(const float* __restrict__ Wz, const float* __restrict__ Wh)
{
    size_t i = ((size_t)blockIdx.x * 256 + threadIdx.x) * 4;
    uint2 hu, lu;
    split4(*reinterpret_cast<const float4*>(&Wz[i]), hu, lu);
    *reinterpret_cast<uint2*>(&g_wzh[i]) = hu;
    *reinterpret_cast<uint2*>(&g_wzl[i]) = lu;
    split4(*reinterpret_cast<const float4*>(&Wh[i]), hu, lu);
    *reinterpret_cast<uint2*>(&g_whh[i]) = hu;
    *reinterpret_cast<uint2*>(&g_whl[i]) = lu;
}

// ---------------------------------------------------------------------------
// cp.async one K-chunk (32) stage into smem buffer. 256 threads, 8 CP16 each.
// ---------------------------------------------------------------------------
__device__ __forceinline__ void copy_stage(uint32_t sa, int m0, int n0, int k0, int tid)
{
    // x hi/lo: 128 rows x 64B = 512 x 16B per matrix -> 2 per thread each
    #pragma unroll
    for (int i = 0; i < 2; i++) {
        int f = tid + i * 256;
        int row = f >> 2, c = f & 3;
        uint32_t d = sa + row * RS + c * 16;
        size_t   s = (size_t)(m0 + row) * D_ + k0 + c * 8;
        CP16(d + OX_H, &g_xh[s]);
        CP16(d + OX_L, &g_xl[s]);
    }
    // W: 64 rows x 64B = 256 x 16B per matrix -> 1 per thread per matrix
    {
        int row = tid >> 2, c = tid & 3;
        uint32_t d = sa + row * RS + c * 16;
        size_t   s = (size_t)(n0 + row) * D_ + k0 + c * 8;
        CP16(d + OW0H, &g_wzh[s]);
        CP16(d + OW0L, &g_wzl[s]);
        CP16(d + OW1H, &g_whh[s]);
        CP16(d + OW1L, &g_whl[s]);
    }
}

// ---------------------------------------------------------------------------
// Kernel 1: dual-output split-bf16 mma.sync GEMM + fused gate epilogue.
//   8 warps, warp tile 32x32, each warp computes BOTH accK (x*Wz^T) and
//   accA (x*Wh^T); A fragments shared, epilogue fully in-register.
// ---------------------------------------------------------------------------
__global__ __launch_bounds__(256, 2)
void gemm_gate_mma(const float* __restrict__ bh, const float* __restrict__ bz)
{
    extern __shared__ char smem[];
    const int tid  = threadIdx.x;
    const int wid  = tid >> 5;
    const int lane = tid & 31;
    const int n0   = blockIdx.x * BN;
    const int m0   = blockIdx.y * BM;
    const int wm   = wid >> 1;          // 0..3 : 32-row tile
    const int wn   = wid & 1;           // 0..1 : 32-col tile

    float accK[32], accA[32];
    #pragma unroll
    for (int i = 0; i < 32; i++) { accK[i] = 0.f; accA[i] = 0.f; }

    const uint32_t sm0 = smem_u32(smem);
    // A ldmatrix lane address (per ms tile of 16 rows): row = wm*32 + (lane&15)
    const uint32_t aBase = sm0 + (uint32_t)(wm * 32 + (lane & 15)) * RS + (lane >> 4) * 16;
    // B ldmatrix lane address: nrow = wn*32 + (lane>>4)*8 + (lane&7)
    const uint32_t bBase = sm0 + (uint32_t)(wn * 32 + ((lane >> 4) << 3) + (lane & 7)) * RS
                           + ((lane >> 3) & 1) * 16;

    copy_stage(sm0, m0, n0, 0, tid);
    CP_COMMIT();

    for (int kc = 0; kc < NKC; kc++) {
        if (kc + 1 < NKC) {
            copy_stage(sm0 + (uint32_t)((kc + 1) & 1) * SSTR, m0, n0, (kc + 1) * KCH, tid);
            CP_COMMIT();
            CP_WAIT(1);
        } else {
            CP_WAIT(0);
        }
        __syncthreads();

        const uint32_t ss = (uint32_t)(kc & 1) * SSTR;
        #pragma unroll
        for (int kk = 0; kk < 2; kk++) {
            const uint32_t ko = kk * 32;
            uint32_t ah[2][4], al[2][4];
            #pragma unroll
            for (int ms = 0; ms < 2; ms++) {
                ldsm_x4(ah[ms], aBase + ss + OX_H + ms * (16 * RS) + ko);
                ldsm_x4(al[ms], aBase + ss + OX_L + ms * (16 * RS) + ko);
            }
            uint32_t bhf[2][4], blf[2][4];
            // ---- Wz -> accK ----
            #pragma unroll
            for (int i = 0; i < 2; i++) {
                ldsm_x4(bhf[i], bBase + ss + OW0H + i * (16 * RS) + ko);
                ldsm_x4(blf[i], bBase + ss + OW0L + i * (16 * RS) + ko);
            }
            #pragma unroll
            for (int ms = 0; ms < 2; ms++)
                #pragma unroll
                for (int ns = 0; ns < 4; ns++) {
                    float* d = accK + (ms * 4 + ns) * 4;
                    const uint32_t* b_h = &bhf[ns >> 1][(ns & 1) * 2];
                    const uint32_t* b_l = &blf[ns >> 1][(ns & 1) * 2];
                    mma_bf16(d, ah[ms], b_h);
                    mma_bf16(d, al[ms], b_h);
                    mma_bf16(d, ah[ms], b_l);
                }
            // ---- Wh -> accA (reuse B fragment registers) ----
            #pragma unroll
            for (int i = 0; i < 2; i++) {
                ldsm_x4(bhf[i], bBase + ss + OW1H + i * (16 * RS) + ko);
                ldsm_x4(blf[i], bBase + ss + OW1L + i * (16 * RS) + ko);
            }
            #pragma unroll
            for (int ms = 0; ms < 2; ms++)
                #pragma unroll
                for (int ns = 0; ns < 4; ns++) {
                    float* d = accA + (ms * 4 + ns) * 4;
                    const uint32_t* b_h = &bhf[ns >> 1][(ns & 1) * 2];
                    const uint32_t* b_l = &blf[ns >> 1][(ns & 1) * 2];
                    mma_bf16(d, ah[ms], b_h);
                    mma_bf16(d, al[ms], b_h);
                    mma_bf16(d, ah[ms], b_l);
                }
        }
        __syncthreads();
    }

    // ---- epilogue: fully in-register (k and a live in the same thread) ----
    #pragma unroll
    for (int ms = 0; ms < 2; ms++)
        #pragma unroll
        for (int ns = 0; ns < 4; ns++) {
            const int idx = (ms * 4 + ns) * 4;
            const int nl  = wn * 32 + ns * 8 + (lane & 3) * 2;
            const int ng  = n0 + nl;
            const int ml  = wm * 32 + ms * 16 + (lane >> 2);
            const float bz0 = bz[ng], bz1 = bz[ng + 1];
            const float bh0 = bh[ng], bh1 = bh[ng + 1];
            #pragma unroll
            for (int rh = 0; rh < 2; rh++) {
                const int m = m0 + ml + rh * 8;
                float c0, v0, c1, v1;
                gate(accK[idx + rh * 2 + 0] + bz0, accA[idx + rh * 2 + 0] + bh0, c0, v0);
                gate(accK[idx + rh * 2 + 1] + bz1, accA[idx + rh * 2 + 1] + bh1, c1, v1);
                size_t o = (size_t)m * H_ + ng;
                *reinterpret_cast<float2*>(&g_c[o]) = make_float2(c0, c1);
                *reinterpret_cast<float2*>(&g_v[o]) = make_float2(v0, v1);
            }
        }
}

// ---------------------------------------------------------------------------
// Kernel 2: per-chunk affine summaries.  h_out = A * h_in + B  over TC steps.
// ---------------------------------------------------------------------------
__global__ void scan_pass1()
{
    const int h     = threadIdx.x;
    const int chunk = blockIdx.x;
    const int b     = blockIdx.y;
    size_t base = ((size_t)(b * T_ + chunk * TC)) * H_ + h;
    float A = 1.f, Bv = 0.f;
    #pragma unroll 4
    for (int t = 0; t < TC; t++) {
        float cc = g_c[base];
        float vv = g_v[base];
        Bv = fmaf(cc, Bv, vv);
        A *= cc;
        base += H_;
    }
    int o = (b * NCHUNK + chunk) * H_ + h;
    g_sumA[o] = A;
    g_sumB[o] = Bv;
}

// ---------------------------------------------------------------------------
// Kernel 3: sequential combine over chunks -> carry-in per chunk.
// ---------------------------------------------------------------------------
__global__ void scan_pass2(const float* __restrict__ h_prev)
{
    const int h = threadIdx.x;
    const int b = blockIdx.x;
    float carry = h_prev[b * H_ + h];
    #pragma unroll
    for (int j = 0; j < NCHUNK; j++) {
        int o = (b * NCHUNK + j) * H_ + h;
        g_carry[o] = carry;
        carry = fmaf(g_sumA[o], carry, g_sumB[o]);
    }
}

// ---------------------------------------------------------------------------
// Kernel 4: replay chunk scan with correct carry, write output.
// ---------------------------------------------------------------------------
__global__ void scan_pass3(float* __restrict__ out)
{
    const int h     = threadIdx.x;
    const int chunk = blockIdx.x;
    const int b     = blockIdx.y;
    float hc = g_carry[(b * NCHUNK + chunk) * H_ + h];
    size_t base = ((size_t)(b * T_ + chunk * TC)) * H_ + h;
    #pragma unroll 4
    for (int t = 0; t < TC; t++) {
        hc = fmaf(g_c[base], hc, g_v[base]);
        out[base] = hc;
        base += H_;
    }
}

// ---------------------------------------------------------------------------
extern "C" void kernel_launch(void* const* d_in, const int* in_sizes, int n_in,
                              void* d_out, int out_size)
{
    const float* x      = (const float*)d_in[0];  // (B,T,D)
    const float* h_prev = (const float*)d_in[1];  // (B,1,H)
    const float* W_h    = (const float*)d_in[2];  // (H,D)
    const float* b_h    = (const float*)d_in[3];  // (H)
    const float* W_z    = (const float*)d_in[4];  // (H,D)
    const float* b_z    = (const float*)d_in[5];  // (H)
    float* out = (float*)d_out;                   // (B,T,H)

    cudaFuncSetAttribute(gemm_gate_mma, cudaFuncAttributeMaxDynamicSharedMemorySize, SMEM_BYTES);

    split_x<<<(M_ * D_) / (256 * 4), 256>>>(x);
    split_w<<<(H_ * D_) / (256 * 4), 256>>>(W_z, W_h);

    dim3 gemm_grid(H_ / BN, M_ / BM);             // (8, 256)
    gemm_gate_mma<<<gemm_grid, 256, SMEM_BYTES>>>(b_h, b_z);

    scan_pass1<<<dim3(NCHUNK, B_), H_>>>();
    scan_pass2<<<B_, H_>>>(h_prev);
    scan_pass3<<<dim3(NCHUNK, B_), H_>>>(out);
}